// round 1
// baseline (speedup 1.0000x reference)
#include <cuda_runtime.h>

#define BATCH 4
#define NTOK 4096        // H*W = 64*64
#define CDIM 64
#define DDIM 8
#define QB 128           // queries per block
#define KB 128           // keys per chunk

// scratch (device globals: no allocation allowed in kernel_launch)
__device__ float g_q[BATCH * NTOK * DDIM];
__device__ float g_k[BATCH * NTOK * DDIM];
__device__ float g_v[BATCH * NTOK * CDIM];

// ---------------------------------------------------------------------------
// Projection: q = x@Wf + bf, k = x@Wg + bg, v = x@Wh + bh
// One thread per row (64 rows / block, 64 threads). Weights transposed in
// smem so the inner loop is broadcast LDS.128 + FFMA with x in registers.
// ---------------------------------------------------------------------------
__global__ __launch_bounds__(64) void proj_kernel(
    const float* __restrict__ x,
    const float* __restrict__ Wf, const float* __restrict__ bf,
    const float* __restrict__ Wg, const float* __restrict__ bg,
    const float* __restrict__ Wh, const float* __restrict__ bh)
{
    __shared__ float xs[64][68];     // 64 rows of x, padded for conflict-free LDS.128
    __shared__ float WhT[64][64];    // WhT[ch][c] = Wh[c][ch]
    __shared__ float bias[CDIM];

    const int tid = threadIdx.x;
    const int rowbase = blockIdx.x * 64;

    // stage x rows (coalesced)
    for (int i = tid; i < 64 * 64; i += 64) {
        xs[i >> 6][i & 63] = x[rowbase * 64 + i];
    }
    // stage Wh transposed (coalesced read)
    for (int i = tid; i < 64 * 64; i += 64) {
        WhT[i & 63][i >> 6] = Wh[i];
    }
    bias[tid] = bh[tid];
    __syncthreads();

    // pull my x row into registers (padded stride -> conflict-free)
    float xr[64];
#pragma unroll
    for (int c4 = 0; c4 < 16; c4++) {
        float4 t = *(const float4*)&xs[tid][c4 * 4];
        xr[c4 * 4 + 0] = t.x; xr[c4 * 4 + 1] = t.y;
        xr[c4 * 4 + 2] = t.z; xr[c4 * 4 + 3] = t.w;
    }

    const int row = rowbase + tid;

    // v = x @ Wh + bh   (64 channels)
#pragma unroll 1
    for (int ch = 0; ch < CDIM; ch++) {
        float a = bias[ch];
        const float4* w = (const float4*)&WhT[ch][0];   // broadcast across warp
#pragma unroll
        for (int c4 = 0; c4 < 16; c4++) {
            float4 ww = w[c4];
            a += xr[c4 * 4 + 0] * ww.x;
            a += xr[c4 * 4 + 1] * ww.y;
            a += xr[c4 * 4 + 2] * ww.z;
            a += xr[c4 * 4 + 3] * ww.w;
        }
        g_v[row * CDIM + ch] = a;
    }

    // q = x @ Wf + bf, k = x @ Wg + bg   (8 channels each; weights read
    // straight from global — tiny, broadcast, L1-resident)
#pragma unroll 1
    for (int ch = 0; ch < DDIM; ch++) {
        float aq = bf[ch];
        float ak = bg[ch];
#pragma unroll
        for (int c = 0; c < CDIM; c++) {
            aq += xr[c] * Wf[c * DDIM + ch];
            ak += xr[c] * Wg[c * DDIM + ch];
        }
        g_q[row * DDIM + ch] = aq;
        g_k[row * DDIM + ch] = ak;
    }
}

// ---------------------------------------------------------------------------
// Flash attention: s = q k^T (no scaling), softmax over keys, o = s v,
// out = gamma*o + x.
// Block: 128 queries, 256 threads (2 threads per query, 32 V-channels each).
// K/V chunk staged in smem; inner loop is warp-broadcast LDS (conflict-free).
// Online softmax staged per 16-key sub-tile (rescale amortized to 2 mult/key).
// ---------------------------------------------------------------------------
__global__ __launch_bounds__(256) void attn_kernel(
    const float* __restrict__ x,
    const float* __restrict__ gamma_p,
    float* __restrict__ out)
{
    __shared__ float Ks[KB * DDIM];   // 4 KB
    __shared__ float Vs[KB * CDIM];   // 32 KB

    const int tid  = threadIdx.x;
    const int qi   = tid & 127;       // query within block
    const int half = tid >> 7;        // which 32-channel half of V/out
    const int b    = blockIdx.y;
    const int qrow = blockIdx.x * QB + qi;

    const float* qptr = &g_q[(b * NTOK + qrow) * DDIM];
    const float4 q0 = *(const float4*)qptr;
    const float4 q1 = *(const float4*)(qptr + 4);

    float m = -1e30f, l = 0.0f;
    float acc[32];
#pragma unroll
    for (int c = 0; c < 32; c++) acc[c] = 0.0f;

    const float* kbase = &g_k[b * NTOK * DDIM];
    const float* vbase = &g_v[b * NTOK * CDIM];

    for (int k0 = 0; k0 < NTOK; k0 += KB) {
        __syncthreads();  // previous chunk fully consumed
        // K chunk: 1024 floats = 256 float4, one per thread (coalesced)
        ((float4*)Ks)[tid] = ((const float4*)(kbase + k0 * DDIM))[tid];
        // V chunk: 8192 floats = 2048 float4, 8 per thread (coalesced)
        const float4* vsrc = (const float4*)(vbase + k0 * CDIM);
#pragma unroll
        for (int i = 0; i < 8; i++)
            ((float4*)Vs)[tid + i * 256] = vsrc[tid + i * 256];
        __syncthreads();

#pragma unroll 1
        for (int j0 = 0; j0 < KB; j0 += 16) {
            float s[16];
            float lm = -1e30f;
#pragma unroll
            for (int jj = 0; jj < 16; jj++) {
                const float4 ka = *(const float4*)&Ks[(j0 + jj) * DDIM];
                const float4 kb2 = *(const float4*)&Ks[(j0 + jj) * DDIM + 4];
                float sv = q0.x * ka.x + q0.y * ka.y + q0.z * ka.z + q0.w * ka.w
                         + q1.x * kb2.x + q1.y * kb2.y + q1.z * kb2.z + q1.w * kb2.w;
                s[jj] = sv;
                lm = fmaxf(lm, sv);
            }
            const float mnew  = fmaxf(m, lm);
            const float scale = __expf(m - mnew);
            m = mnew;
            l *= scale;
#pragma unroll
            for (int c = 0; c < 32; c++) acc[c] *= scale;
#pragma unroll
            for (int jj = 0; jj < 16; jj++) {
                const float p = __expf(s[jj] - m);
                l += p;
                const float4* vr = (const float4*)&Vs[(j0 + jj) * CDIM + half * 32];
#pragma unroll
                for (int cc = 0; cc < 8; cc++) {
                    const float4 vv = vr[cc];   // warp-broadcast
                    acc[cc * 4 + 0] += p * vv.x;
                    acc[cc * 4 + 1] += p * vv.y;
                    acc[cc * 4 + 2] += p * vv.z;
                    acc[cc * 4 + 3] += p * vv.w;
                }
            }
        }
    }

    const float inv   = 1.0f / l;
    const float gamma = *gamma_p;
    const int   obase = (b * NTOK + qrow) * CDIM + half * 32;
#pragma unroll
    for (int cc = 0; cc < 8; cc++) {
        const float4 xv = *(const float4*)&x[obase + cc * 4];
        float4 ov;
        ov.x = gamma * acc[cc * 4 + 0] * inv + xv.x;
        ov.y = gamma * acc[cc * 4 + 1] * inv + xv.y;
        ov.z = gamma * acc[cc * 4 + 2] * inv + xv.z;
        ov.w = gamma * acc[cc * 4 + 3] * inv + xv.w;
        *(float4*)&out[obase + cc * 4] = ov;
    }
}

extern "C" void kernel_launch(void* const* d_in, const int* in_sizes, int n_in,
                              void* d_out, int out_size)
{
    const float* x     = (const float*)d_in[0];
    const float* Wf    = (const float*)d_in[1];
    const float* bf    = (const float*)d_in[2];
    const float* Wg    = (const float*)d_in[3];
    const float* bg    = (const float*)d_in[4];
    const float* Wh    = (const float*)d_in[5];
    const float* bh    = (const float*)d_in[6];
    const float* gamma = (const float*)d_in[7];
    float* out = (float*)d_out;

    proj_kernel<<<(BATCH * NTOK) / 64, 64>>>(x, Wf, bf, Wg, bg, Wh, bh);
    attn_kernel<<<dim3(NTOK / QB, BATCH), 256>>>(x, gamma, out);
}